// round 12
// baseline (speedup 1.0000x reference)
#include <cuda_runtime.h>
#include <cuda_bf16.h>
#include <cstdint>

#define BSZ   512
#define NNODE 22
#define INDIM 128
#define HID   256

// Scratch (device globals) — activations & weights pre-split (bf16 hi/lo)
__device__ __nv_bfloat16 g_hsh[BSZ * HID], g_hsl[BSZ * HID];
__device__ __nv_bfloat16 g_Sh [BSZ * HID], g_Sl [BSZ * HID];
__device__ __nv_bfloat16 g_th [BSZ * HID], g_tl [BSZ * HID];
__device__ __nv_bfloat16 g_Wth[3 * HID * HID], g_Wtl[3 * HID * HID]; // [n][k]

// dataflow counters (+paired done counters for self-reset across graph replays)
__device__ unsigned g_cW[3][8], g_dW[3][8];   // weight slices: 1 prod / 32 wait
__device__ unsigned g_cH[32],   g_dH[32];     // hs row-groups: 8 prod / 8 wait
__device__ unsigned g_cA[2][32], g_dA[2][32]; // L0/L1 tiles:   8 prod / 8 wait

// ---------------------------------------------------------------------------
// bf16 split-2 helpers
// ---------------------------------------------------------------------------
__device__ __forceinline__ void bf16_split2(float v0, float v1,
                                            uint32_t& hi, uint32_t& lo) {
    __nv_bfloat162 h = __float22bfloat162_rn(make_float2(v0, v1));
    float2 hf = __bfloat1622float2(h);
    __nv_bfloat162 l = __float22bfloat162_rn(make_float2(v0 - hf.x, v1 - hf.y));
    hi = *reinterpret_cast<uint32_t*>(&h);
    lo = *reinterpret_cast<uint32_t*>(&l);
}

__device__ __forceinline__ void split1(float v, __nv_bfloat16& h, __nv_bfloat16& l) {
    h = __float2bfloat16_rn(v);
    l = __float2bfloat16_rn(v - __bfloat162float(h));
}

__device__ __forceinline__ void mma_bf16(float* d, const uint32_t* a,
                                         uint32_t b0, uint32_t b1) {
    asm volatile(
        "mma.sync.aligned.m16n8k16.row.col.f32.bf16.bf16.f32 "
        "{%0,%1,%2,%3}, {%4,%5,%6,%7}, {%8,%9}, {%0,%1,%2,%3};"
        : "+f"(d[0]), "+f"(d[1]), "+f"(d[2]), "+f"(d[3])
        : "r"(a[0]), "r"(a[1]), "r"(a[2]), "r"(a[3]), "r"(b0), "r"(b1));
}

__device__ __forceinline__ uint32_t lds_u32(const __nv_bfloat16* p) {
    return *reinterpret_cast<const uint32_t*>(p);
}

// ---------------------------------------------------------------------------
// Dataflow sync primitives.
// block_arrive: publish this block's global writes, then bump the counter.
// block_wait:   spin until cnt>=tgt (acquire), then self-reset via done pair:
//               the LAST of nwait waiters zeroes both (all waiters have
//               already observed cnt by then). Leaves counters 0 for the next
//               graph replay — deterministic.
// ---------------------------------------------------------------------------
__device__ __forceinline__ void block_arrive(unsigned* cnt) {
    __threadfence();
    __syncthreads();
    if (threadIdx.x == 0) atomicAdd(cnt, 1u);
}

__device__ __forceinline__ void block_wait(unsigned* cnt, unsigned tgt,
                                           unsigned* done, unsigned nwait) {
    if (threadIdx.x == 0) {
        volatile unsigned* c = cnt;
        while (*c < tgt) { }
        __threadfence();                       // acquire
        if (atomicAdd(done, 1u) + 1u == nwait) {
            *(volatile unsigned*)cnt  = 0u;    // self-reset for next replay
            *(volatile unsigned*)done = 0u;
        }
    }
    __syncthreads();
}

// ---------------------------------------------------------------------------
// Tail layer (256 threads): 16 rows x 32 cols, 8-way split-K (32 k per warp).
// ---------------------------------------------------------------------------
template <bool RELU, bool BCAST>
__device__ __forceinline__ void tail_layer(
    unsigned char* sm,
    const __nv_bfloat16* __restrict__ Ahg, const __nv_bfloat16* __restrict__ Alg,
    const __nv_bfloat16* __restrict__ Wh,  const __nv_bfloat16* __restrict__ Wl,
    const float* __restrict__ bias, float biasScale,
    float* __restrict__ Cf,
    __nv_bfloat16* __restrict__ Chg, __nv_bfloat16* __restrict__ Clg,
    int m0, int n0) {
    __nv_bfloat16* Ah = (__nv_bfloat16*)sm;             // [16][256] (8KB)
    __nv_bfloat16* Al = (__nv_bfloat16*)(sm + 8192);
    __nv_bfloat16* Bh = (__nv_bfloat16*)(sm + 16384);   // [32][256] (16KB)
    __nv_bfloat16* Bl = (__nv_bfloat16*)(sm + 32768);
    typedef float RedT[16][33];
    RedT* red = (RedT*)sm;            // [8][16][33] f32 = 16896B, aliases A+B

    const int t  = threadIdx.x;
    const int w  = t >> 5;            // k-slice 0..7 (32 k each)
    const int l  = t & 31;
    const int g  = l >> 2;
    const int t4 = l & 3;

    // ---- stage A [16 x 256] (2 uint4/thread/array) + B^T [32 x 256] (4) ----
#pragma unroll
    for (int j = 0; j < 2; j++) {
        int flat = j * 256 + t;            // uint4 index over [16][32]
        int m   = flat >> 5;
        int kq8 = (flat & 31) * 8;
        int kx  = kq8 ^ (8 * (m & 7));
        *(uint4*)&Ah[m * 256 + kx] = *(const uint4*)&Ahg[(size_t)(m0 + m) * HID + kq8];
        *(uint4*)&Al[m * 256 + kx] = *(const uint4*)&Alg[(size_t)(m0 + m) * HID + kq8];
    }
#pragma unroll
    for (int j = 0; j < 4; j++) {
        int flat = j * 256 + t;            // uint4 index over [32][32]
        int n   = flat >> 5;
        int kq8 = (flat & 31) * 8;
        int kx  = kq8 ^ (8 * (n & 7));
        *(uint4*)&Bh[n * 256 + kx] = *(const uint4*)&Wh[(size_t)(n0 + n) * HID + kq8];
        *(uint4*)&Bl[n * 256 + kx] = *(const uint4*)&Wl[(size_t)(n0 + n) * HID + kq8];
    }
    __syncthreads();

    float acc[4][4];
#pragma unroll
    for (int nt = 0; nt < 4; nt++)
#pragma unroll
        for (int j = 0; j < 4; j++) acc[nt][j] = 0.0f;

#pragma unroll
    for (int ks = 0; ks < 2; ks++) {
        const int kb  = 32 * w + 16 * ks;
        const int ka0 = (kb + 2 * t4) ^ (8 * g);
        const int ka2 = (kb + 2 * t4 + 8) ^ (8 * g);

        uint32_t ah[4], al[4];
        ah[0] = lds_u32(Ah + g * 256 + ka0);
        ah[1] = lds_u32(Ah + (g + 8) * 256 + ka0);
        ah[2] = lds_u32(Ah + g * 256 + ka2);
        ah[3] = lds_u32(Ah + (g + 8) * 256 + ka2);
        al[0] = lds_u32(Al + g * 256 + ka0);
        al[1] = lds_u32(Al + (g + 8) * 256 + ka0);
        al[2] = lds_u32(Al + g * 256 + ka2);
        al[3] = lds_u32(Al + (g + 8) * 256 + ka2);

#pragma unroll
        for (int nt = 0; nt < 4; nt++) {
            const int n = nt * 8 + g;
            uint32_t bh0 = lds_u32(Bh + n * 256 + ka0);
            uint32_t bh1 = lds_u32(Bh + n * 256 + ka2);
            uint32_t bl0 = lds_u32(Bl + n * 256 + ka0);
            uint32_t bl1 = lds_u32(Bl + n * 256 + ka2);
            mma_bf16(acc[nt], ah, bh0, bh1);
            mma_bf16(acc[nt], ah, bl0, bl1);
            mma_bf16(acc[nt], al, bh0, bh1);
        }
    }
    __syncthreads();   // A/B reads done -> red may alias

    // ---- 8-way split-K reduce via smem ----
#pragma unroll
    for (int nt = 0; nt < 4; nt++) {
        const int col = nt * 8 + 2 * t4;
        red[w][g][col]         = acc[nt][0];
        red[w][g][col + 1]     = acc[nt][1];
        red[w][g + 8][col]     = acc[nt][2];
        red[w][g + 8][col + 1] = acc[nt][3];
    }
    __syncthreads();

    // ---- epilogue: thread owns 2 cols of one row ----
    const int row = t >> 4;            // 0..15
    const int c2  = (t & 15) * 2;      // 0..30
    float v0 = 0.0f, v1 = 0.0f;
#pragma unroll
    for (int w8 = 0; w8 < 8; w8++) {
        v0 += red[w8][row][c2];
        v1 += red[w8][row][c2 + 1];
    }
    v0 += biasScale * bias[n0 + c2];
    v1 += biasScale * bias[n0 + c2 + 1];
    if (RELU) { v0 = fmaxf(v0, 0.0f); v1 = fmaxf(v1, 0.0f); }

    const int rowg = m0 + row;
    const int colg = n0 + c2;
    if (!BCAST) {
        __nv_bfloat16 h0, l0, h1, l1;
        split1(v0, h0, l0);
        split1(v1, h1, l1);
        __nv_bfloat16 hp[2] = {h0, h1}, lp[2] = {l0, l1};
        *(uint32_t*)&Chg[(size_t)rowg * HID + colg] = *(uint32_t*)hp;
        *(uint32_t*)&Clg[(size_t)rowg * HID + colg] = *(uint32_t*)lp;
    } else {
        const float2 ov = make_float2(v0, v1);
        size_t base = ((size_t)rowg * NNODE) * HID + colg;
#pragma unroll
        for (int p = 0; p < NNODE; p++)
            *(float2*)&Cf[base + (size_t)p * HID] = ov;
    }
    __syncthreads();   // red/A free before any next staging
}

// ---------------------------------------------------------------------------
// Fully fused kernel: weight prep + K1 + 3 tail layers, one launch.
// 256 blocks x 256 threads, 48KB static smem, forced 2 blocks/SM ->
// capacity 296 >= 256 -> single wave -> dataflow spins cannot deadlock.
// ---------------------------------------------------------------------------
__global__ void __launch_bounds__(256, 2)
fused_all(const float* __restrict__ x,
          const float* __restrict__ We1, const float* __restrict__ be1,
          const float* __restrict__ We2, const float* __restrict__ be2,
          const float* __restrict__ Wn1, const float* __restrict__ bn1,
          const float* __restrict__ Wn2, const float* __restrict__ bn2,
          float* __restrict__ out) {
    __shared__ __align__(16) unsigned char sm[49152];

    const int b = blockIdx.x;
    const int t = threadIdx.x;

    // ======== Phase 0: weight transpose + split (blocks 0..23) ========
    if (b < 24) {
        const int mat = b >> 3;            // 0..2
        const int ns  = b & 7;             // 32-row n slice
        const float* Wsrc = (mat == 0) ? We2 : (mat == 1) ? Wn1 : Wn2;
        __nv_bfloat16* dh = g_Wth + mat * HID * HID;
        __nv_bfloat16* dl = g_Wtl + mat * HID * HID;
        const int n   = ns * 32 + (t & 31);
        const int kb0 = (t >> 5) * 32;
        for (int kq = 0; kq < 32; kq += 4) {
            __nv_bfloat16 h[4], l[4];
#pragma unroll
            for (int i = 0; i < 4; i++)
                split1(Wsrc[(size_t)(kb0 + kq + i) * HID + n], h[i], l[i]);
            *(uint2*)&dh[(size_t)n * HID + kb0 + kq] = *(uint2*)h;
            *(uint2*)&dl[(size_t)n * HID + kb0 + kq] = *(uint2*)l;
        }
        block_arrive(&g_cW[mat][ns]);
    }

    // ======== Phase 1: K1 (all blocks; cx = b&3, cy = b>>2) ========
    {
        __nv_bfloat16* Ah = (__nv_bfloat16*)sm;                // [176][40]
        __nv_bfloat16* Al = (__nv_bfloat16*)(sm + 14080);
        __nv_bfloat16* Bh = (__nv_bfloat16*)(sm + 28160);      // [64][40]
        __nv_bfloat16* Bl = (__nv_bfloat16*)(sm + 33280);
        float* hb = (float*)sm;                                // [176][68]

        const int w  = t >> 5;
        const int l  = t & 31;
        const int g  = l >> 2;
        const int t4 = l & 3;
        const int cx = b & 3;
        const int cy = b >> 2;
        const int n0 = cx * 64;
        const int m0 = cy * 176;

        float acc[11][4];
#pragma unroll
        for (int mt = 0; mt < 11; mt++)
#pragma unroll
            for (int j = 0; j < 4; j++) acc[mt][j] = 0.0f;

        for (int kc = 0; kc < 4; kc++) {
            const int k0 = kc * 32;
#pragma unroll
            for (int j = 0; j < 6; j++) {
                int flat = j * 256 + t;
                if (flat < 1408) {
                    int m  = flat >> 3;
                    int kq = (flat & 7) * 4;
                    float4 v = *(const float4*)&x[(size_t)(m0 + m) * INDIM + k0 + kq];
                    uint32_t h0, l0, h1, l1;
                    bf16_split2(v.x, v.y, h0, l0);
                    bf16_split2(v.z, v.w, h1, l1);
                    *(uint32_t*)&Ah[m * 40 + kq]     = h0;
                    *(uint32_t*)&Ah[m * 40 + kq + 2] = h1;
                    *(uint32_t*)&Al[m * 40 + kq]     = l0;
                    *(uint32_t*)&Al[m * 40 + kq + 2] = l1;
                }
            }
#pragma unroll
            for (int j = 0; j < 8; j++) {
                int flat = j * 256 + t;
                int kl = flat >> 6;
                int n  = flat & 63;
                float v = We1[(size_t)(k0 + kl) * HID + n0 + n]
                        + We1[(size_t)(k0 + kl + INDIM) * HID + n0 + n];
                split1(v, Bh[n * 40 + kl], Bl[n * 40 + kl]);
            }
            __syncthreads();

#pragma unroll
            for (int ks = 0; ks < 2; ks++) {
                const int kb = ks * 16 + 2 * t4;
                uint32_t bh0 = lds_u32(Bh + (8 * w + g) * 40 + kb);
                uint32_t bh1 = lds_u32(Bh + (8 * w + g) * 40 + kb + 8);
                uint32_t bl0 = lds_u32(Bl + (8 * w + g) * 40 + kb);
                uint32_t bl1 = lds_u32(Bl + (8 * w + g) * 40 + kb + 8);
#pragma unroll
                for (int mt = 0; mt < 11; mt++) {
                    const int rb = mt * 16;
                    uint32_t ah[4], al[4];
                    ah[0] = lds_u32(Ah + (rb + g) * 40 + kb);
                    ah[1] = lds_u32(Ah + (rb + g + 8) * 40 + kb);
                    ah[2] = lds_u32(Ah + (rb + g) * 40 + kb + 8);
                    ah[3] = lds_u32(Ah + (rb + g + 8) * 40 + kb + 8);
                    al[0] = lds_u32(Al + (rb + g) * 40 + kb);
                    al[1] = lds_u32(Al + (rb + g + 8) * 40 + kb);
                    al[2] = lds_u32(Al + (rb + g) * 40 + kb + 8);
                    al[3] = lds_u32(Al + (rb + g + 8) * 40 + kb + 8);
                    mma_bf16(acc[mt], ah, bh0, bh1);
                    mma_bf16(acc[mt], ah, bl0, bl1);
                    mma_bf16(acc[mt], al, bh0, bh1);
                }
            }
            __syncthreads();
        }

        const int   cc  = 8 * w + 2 * t4;
        const float bv0 = be1[n0 + cc];
        const float bv1 = be1[n0 + cc + 1];
#pragma unroll
        for (int mt = 0; mt < 11; mt++) {
            const int r0 = mt * 16 + g;
            const int r1 = r0 + 8;
            hb[r0 * 68 + cc]     = fmaxf(acc[mt][0] + bv0, 0.0f);
            hb[r0 * 68 + cc + 1] = fmaxf(acc[mt][1] + bv1, 0.0f);
            hb[r1 * 68 + cc]     = fmaxf(acc[mt][2] + bv0, 0.0f);
            hb[r1 * 68 + cc + 1] = fmaxf(acc[mt][3] + bv1, 0.0f);
        }
        __syncthreads();

        {
            const int c = t & 63;
#pragma unroll
            for (int hh = 0; hh < 2; hh++) {
                const int gg = (t >> 6) + hh * 4;
                float s = 0.0f;
#pragma unroll
                for (int i = 0; i < 22; i++)
                    s += hb[(gg * 22 + i) * 68 + c];
                size_t o = (size_t)(cy * 8 + gg) * HID + n0 + c;
                split1(s, g_hsh[o], g_hsl[o]);
            }
        }
    }
    block_arrive(&g_cH[b >> 3]);        // hs row-group mg = cy>>1 = b>>3

    // ======== Phase 2: fused tail (nx = b&7, mg = b>>3) ========
    const int nx  = b & 7;
    const int mg  = b >> 3;
    const int n0t = nx * 32;
    const int m0t = mg * 16;

    // L0: S = hs @ We2 + 22*be2
    block_wait(&g_cW[0][nx], 1u, &g_dW[0][nx], 32u);
    block_wait(&g_cH[mg],    8u, &g_dH[mg],     8u);
    tail_layer<false, false>(sm, g_hsh, g_hsl, g_Wth, g_Wtl,
                             be2, (float)NNODE, nullptr, g_Sh, g_Sl, m0t, n0t);
    block_arrive(&g_cA[0][mg]);

    // L1: t = relu(S @ Wn1 + bn1)
    block_wait(&g_cW[1][nx], 1u, &g_dW[1][nx], 32u);
    block_wait(&g_cA[0][mg], 8u, &g_dA[0][mg],  8u);
    tail_layer<true, false>(sm, g_Sh, g_Sl,
                            g_Wth + HID * HID, g_Wtl + HID * HID,
                            bn1, 1.0f, nullptr, g_th, g_tl, m0t, n0t);
    block_arrive(&g_cA[1][mg]);

    // L2: out = t @ Wn2 + bn2, broadcast over 22 nodes
    block_wait(&g_cW[2][nx], 1u, &g_dW[2][nx], 32u);
    block_wait(&g_cA[1][mg], 8u, &g_dA[1][mg],  8u);
    tail_layer<false, true>(sm, g_th, g_tl,
                            g_Wth + 2 * HID * HID, g_Wtl + 2 * HID * HID,
                            bn2, 1.0f, out, nullptr, nullptr, m0t, n0t);
}

// ---------------------------------------------------------------------------
extern "C" void kernel_launch(void* const* d_in, const int* in_sizes, int n_in,
                              void* d_out, int out_size) {
    const float* x   = (const float*)d_in[0];
    const float* We1 = (const float*)d_in[1];
    const float* be1 = (const float*)d_in[2];
    const float* We2 = (const float*)d_in[3];
    const float* be2 = (const float*)d_in[4];
    const float* Wn1 = (const float*)d_in[5];
    const float* bn1 = (const float*)d_in[6];
    const float* Wn2 = (const float*)d_in[7];
    const float* bn2 = (const float*)d_in[8];
    float* out = (float*)d_out;

    fused_all<<<256, 256>>>(x, We1, be1, We2, be2, Wn1, bn1, Wn2, bn2, out);
}